// round 2
// baseline (speedup 1.0000x reference)
#include <cuda_runtime.h>

// Problem constants
#define B_   8
#define N_   256
#define D_   768
#define D2_  1536
#define H_   12
#define HD_  64
#define R_   10
#define EPS_ 1e-5f
// SCALE^2 / R  = (1/64)/10
#define GSCALE (1.0f / 640.0f)

// ---------------- scratch (device globals; no allocation allowed) ----------------
__device__ float g_k [R_ * N_ * D_];          // ref @ Wk        (2560 x 768)
__device__ float g_Gp[H_ * R_ * HD_ * HD_];   // per-(h,r) partial grams
__device__ float g_G [H_ * HD_ * HD_];        // Gbar_h = (s^2/R) * sum_r k^T k
__device__ float g_qv[B_ * N_ * 2 * D_];      // x @ Wqv         (2048 x 1536)
__device__ float g_M [B_ * H_ * HD_ * HD_];   // Gbar_h @ (q^T v)
__device__ float g_y [B_ * N_ * D_];          // mean_r y, flat   (2048 x 768)
__device__ float g_pr[B_ * N_ * D_];          // proj output pre-LN
__device__ float g_x [B_ * N_ * D_];          // x between steps

// ---------------- generic fp32 GEMM: C = A(MxK) @ B(KxN) [+bias] ----------------
// BM=BN=64, BK=16, 256 threads, 4x4 microtile per thread.
template<bool BIAS>
__global__ __launch_bounds__(256) void sgemm_k(const float* __restrict__ A,
                                               const float* __restrict__ Bm,
                                               const float* __restrict__ bias,
                                               float* __restrict__ C,
                                               int M, int N, int K)
{
    __shared__ float As[16][68];   // padded: transposed A tile
    __shared__ float Bs[16][64];
    const int t  = threadIdx.x;
    const int ty = t >> 4, tx = t & 15;
    const int bm = blockIdx.y * 64;
    const int bn = blockIdx.x * 64;

    const float* Ab = A  + (size_t)bm * K;
    const float* Bb = Bm + bn;

    float acc[4][4] = {};

    for (int k0 = 0; k0 < K; k0 += 16) {
        #pragma unroll
        for (int i = 0; i < 4; i++) {
            int idx = t + i * 256;
            int m = idx >> 4, kk = idx & 15;
            As[kk][m] = Ab[(size_t)m * K + k0 + kk];
        }
        #pragma unroll
        for (int i = 0; i < 4; i++) {
            int idx = t + i * 256;
            int kk = idx >> 6, n = idx & 63;
            Bs[kk][n] = Bb[(size_t)(k0 + kk) * N + n];
        }
        __syncthreads();
        #pragma unroll
        for (int kk = 0; kk < 16; kk++) {
            float4 a = *(const float4*)&As[kk][ty * 4];
            float4 b = *(const float4*)&Bs[kk][tx * 4];
            float av[4] = {a.x, a.y, a.z, a.w};
            float bv[4] = {b.x, b.y, b.z, b.w};
            #pragma unroll
            for (int i = 0; i < 4; i++)
                #pragma unroll
                for (int j = 0; j < 4; j++)
                    acc[i][j] = fmaf(av[i], bv[j], acc[i][j]);
        }
        __syncthreads();
    }

    float4 bb4 = make_float4(0.f, 0.f, 0.f, 0.f);
    if (BIAS) bb4 = *(const float4*)&bias[bn + tx * 4];
    #pragma unroll
    for (int i = 0; i < 4; i++) {
        int m = bm + ty * 4 + i;
        float4 r;
        r.x = acc[i][0] + bb4.x;
        r.y = acc[i][1] + bb4.y;
        r.z = acc[i][2] + bb4.z;
        r.w = acc[i][3] + bb4.w;
        *(float4*)&C[(size_t)m * N + bn + tx * 4] = r;
    }
}

// ---------------- partial gram: for (h,r), P = k_rh^T k_rh (64x64 over 256 rows) ----
__global__ __launch_bounds__(256) void gram_partial_k()
{
    const int h = blockIdx.x, r = blockIdx.y;
    __shared__ float ks[32][64];
    const int t = threadIdx.x, ty = t >> 4, tx = t & 15;

    const float* kb = g_k + (size_t)r * N_ * D_ + h * HD_;
    float acc[4][4] = {};

    for (int c = 0; c < N_; c += 32) {
        #pragma unroll
        for (int i = 0; i < 8; i++) {
            int idx = t + i * 256;
            int nn = idx >> 6, ii = idx & 63;
            ks[nn][ii] = kb[(size_t)(c + nn) * D_ + ii];
        }
        __syncthreads();
        #pragma unroll
        for (int nn = 0; nn < 32; nn++) {
            float4 a = *(const float4*)&ks[nn][ty * 4];
            float4 b = *(const float4*)&ks[nn][tx * 4];
            float av[4] = {a.x, a.y, a.z, a.w};
            float bv[4] = {b.x, b.y, b.z, b.w};
            #pragma unroll
            for (int i = 0; i < 4; i++)
                #pragma unroll
                for (int j = 0; j < 4; j++)
                    acc[i][j] = fmaf(av[i], bv[j], acc[i][j]);
        }
        __syncthreads();
    }

    float* out = g_Gp + ((size_t)h * R_ + r) * (HD_ * HD_);
    #pragma unroll
    for (int i = 0; i < 4; i++) {
        float4 rr;
        rr.x = acc[i][0] * GSCALE; rr.y = acc[i][1] * GSCALE;
        rr.z = acc[i][2] * GSCALE; rr.w = acc[i][3] * GSCALE;
        *(float4*)&out[(ty * 4 + i) * HD_ + tx * 4] = rr;
    }
}

// ---------------- deterministic reduce over r: g_G = sum_r g_Gp ----------------
__global__ __launch_bounds__(256) void gram_reduce_k()
{
    int e = blockIdx.x * 256 + threadIdx.x;          // 0 .. H_*4096-1
    int h = e / (HD_ * HD_);
    int o = e - h * (HD_ * HD_);
    float s = 0.f;
    #pragma unroll
    for (int r = 0; r < R_; r++)
        s += g_Gp[((size_t)h * R_ + r) * (HD_ * HD_) + o];
    g_G[e] = s;
}

// ---------------- per (b,h): P = q^T v; M = Gbar_h @ P ----------------
// Smem lifetimes: {qs,vs} die before Gst is born -> union them (fits 48KB).
__global__ __launch_bounds__(256) void pm_k()
{
    const int bh = blockIdx.x;
    const int b = bh / H_, h = bh % H_;
    __shared__ union {
        struct { float qs[32][64]; float vs[32][64]; } s;
        float Gst[64][68];   // transposed Gbar, padded
    } u;
    __shared__ float Ps[64][64];
    const int t = threadIdx.x, ty = t >> 4, tx = t & 15;

    const float* qb = g_qv + (size_t)b * N_ * D2_ + h * HD_;
    const float* vb = qb + D_;

    float acc[4][4] = {};
    for (int c = 0; c < N_; c += 32) {
        #pragma unroll
        for (int i = 0; i < 8; i++) {
            int idx = t + i * 256;
            int nn = idx >> 6, ii = idx & 63;
            size_t off = (size_t)(c + nn) * D2_ + ii;
            u.s.qs[nn][ii] = qb[off];
            u.s.vs[nn][ii] = vb[off];
        }
        __syncthreads();
        #pragma unroll
        for (int nn = 0; nn < 32; nn++) {
            float4 a = *(const float4*)&u.s.qs[nn][ty * 4];
            float4 b4 = *(const float4*)&u.s.vs[nn][tx * 4];
            float av[4] = {a.x, a.y, a.z, a.w};
            float bv[4] = {b4.x, b4.y, b4.z, b4.w};
            #pragma unroll
            for (int i = 0; i < 4; i++)
                #pragma unroll
                for (int j = 0; j < 4; j++)
                    acc[i][j] = fmaf(av[i], bv[j], acc[i][j]);
        }
        __syncthreads();
    }
    // qs/vs are dead from here on (loop-closing __syncthreads passed).

    // P to smem; Gbar (transposed) into the union region
    #pragma unroll
    for (int i = 0; i < 4; i++) {
        float4 rr = make_float4(acc[i][0], acc[i][1], acc[i][2], acc[i][3]);
        *(float4*)&Ps[ty * 4 + i][tx * 4] = rr;
    }
    const float* Gb = g_G + (size_t)h * (HD_ * HD_);
    #pragma unroll
    for (int i = 0; i < 16; i++) {
        int idx = t + i * 256;
        int ig = idx >> 6, tg = idx & 63;
        u.Gst[tg][ig] = Gb[idx];
    }
    __syncthreads();

    float m4[4][4] = {};
    #pragma unroll
    for (int tt = 0; tt < 64; tt++) {
        float4 a  = *(const float4*)&u.Gst[tt][ty * 4];
        float4 b4 = *(const float4*)&Ps[tt][tx * 4];
        float av[4] = {a.x, a.y, a.z, a.w};
        float bv[4] = {b4.x, b4.y, b4.z, b4.w};
        #pragma unroll
        for (int i = 0; i < 4; i++)
            #pragma unroll
            for (int j = 0; j < 4; j++)
                m4[i][j] = fmaf(av[i], bv[j], m4[i][j]);
    }
    float* Mo = g_M + (size_t)bh * (HD_ * HD_);
    #pragma unroll
    for (int i = 0; i < 4; i++) {
        float4 rr = make_float4(m4[i][0], m4[i][1], m4[i][2], m4[i][3]);
        *(float4*)&Mo[(ty * 4 + i) * HD_ + tx * 4] = rr;
    }
}

// ---------------- per (b,h, n-chunk): y = q @ M, written flat ----------------
__global__ __launch_bounds__(256) void y_k()
{
    const int bh = blockIdx.y;
    const int b = bh / H_, h = bh % H_;
    const int n0 = blockIdx.x * 64;
    __shared__ float qt[64][68];   // transposed q tile, padded
    __shared__ float Ms[64][64];
    const int t = threadIdx.x, ty = t >> 4, tx = t & 15;

    const float* qb = g_qv + (size_t)b * N_ * D2_ + h * HD_;
    const float* Mb = g_M + (size_t)bh * (HD_ * HD_);

    #pragma unroll
    for (int i = 0; i < 16; i++) {
        int idx = t + i * 256;
        int n = idx >> 6, tt = idx & 63;
        qt[tt][n] = qb[(size_t)(n0 + n) * D2_ + tt];
        Ms[n][tt] = Mb[idx];   // n==idx>>6 is the row here too
    }
    __syncthreads();

    float acc[4][4] = {};
    #pragma unroll
    for (int tt = 0; tt < 64; tt++) {
        float4 a  = *(const float4*)&qt[tt][ty * 4];
        float4 b4 = *(const float4*)&Ms[tt][tx * 4];
        float av[4] = {a.x, a.y, a.z, a.w};
        float bv[4] = {b4.x, b4.y, b4.z, b4.w};
        #pragma unroll
        for (int i = 0; i < 4; i++)
            #pragma unroll
            for (int j = 0; j < 4; j++)
                acc[i][j] = fmaf(av[i], bv[j], acc[i][j]);
    }

    // flat layout: g_y[b][h*N*HD + n*HD + hd]  ==  rows of (2048 x 768)
    float* yo = g_y + (size_t)b * (N_ * D_) + (size_t)h * (N_ * HD_);
    #pragma unroll
    for (int i = 0; i < 4; i++) {
        int n = n0 + ty * 4 + i;
        float4 rr = make_float4(acc[i][0], acc[i][1], acc[i][2], acc[i][3]);
        *(float4*)&yo[(size_t)n * HD_ + tx * 4] = rr;
    }
}

// ---------------- layernorm over last dim (768), one block per row ----------------
__global__ __launch_bounds__(256) void ln_k(const float* __restrict__ X,
                                            const float* __restrict__ gamma,
                                            const float* __restrict__ beta,
                                            float* __restrict__ out)
{
    const int row = blockIdx.x;
    const int t = threadIdx.x;
    __shared__ float sx[768];
    __shared__ float wsum[8];
    __shared__ float wsq[8];

    const float* x = X + (size_t)row * D_;
    float s = 0.f;
    #pragma unroll
    for (int i = 0; i < 3; i++) {
        float v = x[t + i * 256];
        sx[t + i * 256] = v;
        s += v;
    }
    #pragma unroll
    for (int o = 16; o; o >>= 1) s += __shfl_xor_sync(0xffffffffu, s, o);
    if ((t & 31) == 0) wsum[t >> 5] = s;
    __syncthreads();
    float tot = 0.f;
    #pragma unroll
    for (int w = 0; w < 8; w++) tot += wsum[w];
    const float mu = tot * (1.0f / 768.0f);

    float vs = 0.f;
    #pragma unroll
    for (int i = 0; i < 3; i++) {
        float d = sx[t + i * 256] - mu;
        vs += d * d;
    }
    #pragma unroll
    for (int o = 16; o; o >>= 1) vs += __shfl_xor_sync(0xffffffffu, vs, o);
    if ((t & 31) == 0) wsq[t >> 5] = vs;
    __syncthreads();
    float tot2 = 0.f;
    #pragma unroll
    for (int w = 0; w < 8; w++) tot2 += wsq[w];
    const float rstd = rsqrtf(tot2 * (1.0f / 768.0f) + EPS_);

    #pragma unroll
    for (int i = 0; i < 3; i++) {
        int c = t + i * 256;
        out[(size_t)row * D_ + c] = (sx[c] - mu) * rstd * gamma[c] + beta[c];
    }
}

// ---------------- host orchestration ----------------
extern "C" void kernel_launch(void* const* d_in, const int* in_sizes, int n_in,
                              void* d_out, int out_size)
{
    const float* x     = (const float*)d_in[0];   // (8,256,768)
    const float* ref   = (const float*)d_in[1];   // (10,256,768)
    const float* Wqv   = (const float*)d_in[2];   // (768,1536)
    const float* Wk    = (const float*)d_in[3];   // (768,768)
    const float* Wproj = (const float*)d_in[4];   // (768,768)
    const float* bproj = (const float*)d_in[5];   // (768)
    const float* gamma = (const float*)d_in[6];   // (768)
    const float* beta  = (const float*)d_in[7];   // (768)
    float* out = (float*)d_out;

    float *pk, *pqv, *py, *ppr, *px;
    cudaGetSymbolAddress((void**)&pk,  g_k);
    cudaGetSymbolAddress((void**)&pqv, g_qv);
    cudaGetSymbolAddress((void**)&py,  g_y);
    cudaGetSymbolAddress((void**)&ppr, g_pr);
    cudaGetSymbolAddress((void**)&px,  g_x);

    // k = ref @ Wk  (2560 x 768 x 768)
    sgemm_k<false><<<dim3(D_ / 64, (R_ * N_) / 64), 256>>>(ref, Wk, nullptr, pk,
                                                           R_ * N_, D_, D_);
    // Gbar_h = (s^2/R) sum_r k^T k   (deterministic two-stage)
    gram_partial_k<<<dim3(H_, R_), 256>>>();
    gram_reduce_k<<<(H_ * HD_ * HD_) / 256, 256>>>();

    for (int step = 0; step < 3; step++) {
        const float* xin = (step == 0) ? x : px;
        float* lnout = (step == 2) ? out : px;

        // qv = x @ Wqv  (2048 x 1536 x 768)
        sgemm_k<false><<<dim3(D2_ / 64, (B_ * N_) / 64), 256>>>(xin, Wqv, nullptr, pqv,
                                                                B_ * N_, D2_, D_);
        // per (b,h): M = Gbar @ (q^T v)
        pm_k<<<B_ * H_, 256>>>();
        // y = q @ M, written as (2048 x 768) flat (mean over r already folded in)
        y_k<<<dim3(N_ / 64, B_ * H_), 256>>>();
        // proj + bias
        sgemm_k<true><<<dim3(D_ / 64, (B_ * N_) / 64), 256>>>(py, Wproj, bproj, ppr,
                                                              B_ * N_, D_, D_);
        // layernorm
        ln_k<<<B_ * N_, 256>>>(ppr, gamma, beta, lnout);
    }
}